// round 3
// baseline (speedup 1.0000x reference)
#include <cuda_runtime.h>
#include <math.h>

#define N_NODES 100000
#define N_EDGES 1200000
#define HID 64
#define G_NUM 128
#define C_OUT 10
#define D_IN 3
#define EPS_BN 1e-5f

// -------- scratch (static device globals; no runtime allocation) --------
__device__ int   g_ecnt[N_NODES];        // in-degree (edges only, no self loop)
__device__ int   g_base[N_NODES];        // CSR segment base (unordered layout)
__device__ int   g_fill[N_NODES];        // fill cursor per node
__device__ int   g_col [N_EDGES];        // src ids grouped by dst
__device__ int   g_tot;                  // global base counter
__device__ float g_dinv[N_NODES];
__device__ float g_xw [N_NODES * HID];   // (h@W) * dinv[i]
__device__ float g_h  [N_NODES * HID];   // layer output
__device__ float g_meanp[G_NUM * HID];
__device__ float g_maxp [G_NUM * HID];
__device__ int   g_cnt  [G_NUM];
__device__ float g_gvec [G_NUM * 2 * HID];

// -------- init --------
__global__ void k_init() {
    int i = blockIdx.x * blockDim.x + threadIdx.x;
    if (i < N_NODES) g_ecnt[i] = 0;
    if (i == 0) g_tot = 0;
}

// -------- in-degree over real edges --------
__global__ void k_deg(const int* __restrict__ ei) {
    int e = blockIdx.x * blockDim.x + threadIdx.x;
    if (e < N_EDGES) atomicAdd(&g_ecnt[ei[N_EDGES + e]], 1);
}

// -------- dinv + CSR bases (warp scan + one atomic per warp) --------
__global__ void k_base() {
    int i = blockIdx.x * blockDim.x + threadIdx.x;
    int lane = threadIdx.x & 31;
    int c = (i < N_NODES) ? g_ecnt[i] : 0;
    if (i < N_NODES) {
        g_dinv[i] = rsqrtf((float)(c + 1));   // +1 self loop
        g_fill[i] = 0;
    }
    // warp inclusive scan of c
    int incl = c;
    #pragma unroll
    for (int off = 1; off < 32; off <<= 1) {
        int v = __shfl_up_sync(0xffffffffu, incl, off);
        if (lane >= off) incl += v;
    }
    int excl = incl - c;
    int wsum = __shfl_sync(0xffffffffu, incl, 31);
    int wbase = 0;
    if (lane == 31) wbase = atomicAdd(&g_tot, wsum);
    wbase = __shfl_sync(0xffffffffu, wbase, 31);
    if (i < N_NODES) g_base[i] = wbase + excl;
}

// -------- CSR fill --------
__global__ void k_fill(const int* __restrict__ ei) {
    int e = blockIdx.x * blockDim.x + threadIdx.x;
    if (e >= N_EDGES) return;
    int s = ei[e];
    int d = ei[N_EDGES + e];
    int pos = atomicAdd(&g_fill[d], 1);
    g_col[g_base[d] + pos] = s;
}

// -------- layer 0 linear: x[N,3] @ W0[3,64], premult dinv --------
__global__ void __launch_bounds__(256) k_lin0(const float* __restrict__ x,
                                              const float* __restrict__ W0) {
    __shared__ float sW[D_IN * HID];
    int t = threadIdx.x;
    if (t < D_IN * HID) sW[t] = W0[t];
    __syncthreads();
    int idx = blockIdx.x * blockDim.x + t;
    if (idx >= N_NODES * HID) return;
    int i = idx >> 6, j = idx & 63;
    float s = x[i * 3 + 0] * sW[j] + x[i * 3 + 1] * sW[64 + j] + x[i * 3 + 2] * sW[128 + j];
    g_xw[idx] = s * g_dinv[i];
}

// -------- hidden linear: g_h[N,64] @ W[64,64], 4 nodes / 256-thread block --------
__global__ void __launch_bounds__(256) k_linh(const float* __restrict__ W) {
    __shared__ float sW[HID * HID];
    __shared__ float sh[4 * HID];
    int t = threadIdx.x;
    for (int q = t; q < HID * HID; q += 256) sW[q] = W[q];
    int local = t >> 6;
    int j = t & 63;
    int i = blockIdx.x * 4 + local;
    if (i < N_NODES) sh[local * HID + j] = g_h[i * HID + j];
    __syncthreads();
    if (i >= N_NODES) return;
    float s = 0.f;
    #pragma unroll
    for (int k = 0; k < HID; k++) s += sh[local * HID + k] * sW[k * HID + j];
    g_xw[i * HID + j] = s * g_dinv[i];
}

// -------- CSR gather + fused epilogue (dinv, bias, BN, relu) --------
__global__ void __launch_bounds__(256) k_gather(const float* __restrict__ b,
                                                const float* __restrict__ gamma,
                                                const float* __restrict__ beta,
                                                const float* __restrict__ mean,
                                                const float* __restrict__ var, int relu) {
    int t = threadIdx.x;
    int node = blockIdx.x * 4 + (t >> 6);
    int j = t & 63;
    if (node >= N_NODES) return;
    int base = g_base[node];
    int cnt  = g_ecnt[node];
    float acc = g_xw[node * HID + j];    // self-loop term
    int k = 0;
    for (; k + 4 <= cnt; k += 4) {
        int s0 = __ldg(&g_col[base + k + 0]);
        int s1 = __ldg(&g_col[base + k + 1]);
        int s2 = __ldg(&g_col[base + k + 2]);
        int s3 = __ldg(&g_col[base + k + 3]);
        float v0 = __ldg(&g_xw[s0 * HID + j]);
        float v1 = __ldg(&g_xw[s1 * HID + j]);
        float v2 = __ldg(&g_xw[s2 * HID + j]);
        float v3 = __ldg(&g_xw[s3 * HID + j]);
        acc += v0 + v1 + v2 + v3;
    }
    for (; k < cnt; k++) {
        int s = __ldg(&g_col[base + k]);
        acc += __ldg(&g_xw[s * HID + j]);
    }
    float v = acc * g_dinv[node] + b[j];
    v = (v - mean[j]) * (gamma[j] * rsqrtf(var[j] + EPS_BN)) + beta[j];
    if (relu) v = fmaxf(v, 0.f);
    g_h[node * HID + j] = v;
}

// -------- pooling --------
__global__ void k_pool_init() {
    int i = blockIdx.x * blockDim.x + threadIdx.x;
    if (i < G_NUM * HID) { g_meanp[i] = 0.f; g_maxp[i] = -INFINITY; }
    if (i < G_NUM) g_cnt[i] = 0;
}
__global__ void __launch_bounds__(256) k_pool(const int* __restrict__ batch) {
    int idx = blockIdx.x * blockDim.x + threadIdx.x;
    if (idx >= N_NODES * HID) return;
    int i = idx >> 6, j = idx & 63;
    int b = __ldg(&batch[i]);
    float v = g_h[idx];
    atomicAdd(&g_meanp[b * HID + j], v);
    if (v >= 0.f) atomicMax((int*)&g_maxp[b * HID + j], __float_as_int(v));
    else          atomicMin((unsigned int*)&g_maxp[b * HID + j], __float_as_uint(v));
    if (j == 0) atomicAdd(&g_cnt[b], 1);
}
__global__ void k_pool_fin() {
    int idx = blockIdx.x * blockDim.x + threadIdx.x;
    if (idx >= G_NUM * HID) return;
    int g = idx >> 6, j = idx & 63;
    float c = (float)g_cnt[g];
    g_gvec[g * 2 * HID + j]       = g_meanp[idx] / c;
    g_gvec[g * 2 * HID + HID + j] = g_maxp[idx];
}

// -------- classifier + log_softmax (one block per graph, 64 threads) --------
__global__ void k_cls(const float* __restrict__ Wc1, const float* __restrict__ bc1,
                      const float* __restrict__ Wc2, const float* __restrict__ bc2,
                      float* __restrict__ out) {
    __shared__ float gv[2 * HID];
    __shared__ float hc[HID];
    __shared__ float lg[C_OUT];
    __shared__ float lse;
    int g = blockIdx.x;
    int t = threadIdx.x;
    gv[t]       = g_gvec[g * 2 * HID + t];
    gv[HID + t] = g_gvec[g * 2 * HID + HID + t];
    __syncthreads();
    float s = bc1[t];
    #pragma unroll
    for (int k = 0; k < 2 * HID; k++) s += gv[k] * Wc1[k * HID + t];
    hc[t] = fmaxf(s, 0.f);
    __syncthreads();
    if (t < C_OUT) {
        float l = bc2[t];
        #pragma unroll
        for (int j = 0; j < HID; j++) l += hc[j] * Wc2[j * C_OUT + t];
        lg[t] = l;
    }
    __syncthreads();
    if (t == 0) {
        float m = -INFINITY;
        #pragma unroll
        for (int c = 0; c < C_OUT; c++) m = fmaxf(m, lg[c]);
        float se = 0.f;
        #pragma unroll
        for (int c = 0; c < C_OUT; c++) se += expf(lg[c] - m);
        lse = m + logf(se);
    }
    __syncthreads();
    if (t < C_OUT) out[g * C_OUT + t] = lg[t] - lse;
}

extern "C" void kernel_launch(void* const* d_in, const int* in_sizes, int n_in,
                              void* d_out, int out_size) {
    const float* x     = (const float*)d_in[0];
    const int*   ei    = (const int*)  d_in[1];
    const int*   batch = (const int*)  d_in[2];
    // d_in[3] = num_graphs (constant 128, unused)
    const float* W0    = (const float*)d_in[4];
    const float* Ws    = (const float*)d_in[5];   // [2,64,64]
    const float* bs    = (const float*)d_in[6];   // [3,64]
    const float* gamma = (const float*)d_in[7];
    const float* beta  = (const float*)d_in[8];
    const float* rmean = (const float*)d_in[9];
    const float* rvar  = (const float*)d_in[10];
    const float* Wc1   = (const float*)d_in[11];
    const float* bc1   = (const float*)d_in[12];
    const float* Wc2   = (const float*)d_in[13];
    const float* bc2   = (const float*)d_in[14];
    float* out = (float*)d_out;

    const int NB_N   = (N_NODES + 255) / 256;
    const int NB_E   = (N_EDGES + 255) / 256;
    const int NB_NH  = (N_NODES * HID + 255) / 256;
    const int NB_LIN = (N_NODES + 3) / 4;

    // CSR build + normalization
    k_init<<<NB_N, 256>>>();
    k_deg <<<NB_E, 256>>>(ei);
    k_base<<<NB_N, 256>>>();
    k_fill<<<NB_E, 256>>>(ei);

    // layer 0
    k_lin0  <<<NB_NH, 256>>>(x, W0);
    k_gather<<<NB_LIN, 256>>>(bs + 0 * HID, gamma + 0 * HID, beta + 0 * HID,
                              rmean + 0 * HID, rvar + 0 * HID, 1);
    // layer 1
    k_linh  <<<NB_LIN, 256>>>(Ws + 0 * HID * HID);
    k_gather<<<NB_LIN, 256>>>(bs + 1 * HID, gamma + 1 * HID, beta + 1 * HID,
                              rmean + 1 * HID, rvar + 1 * HID, 1);
    // layer 2 (no relu)
    k_linh  <<<NB_LIN, 256>>>(Ws + 1 * HID * HID);
    k_gather<<<NB_LIN, 256>>>(bs + 2 * HID, gamma + 2 * HID, beta + 2 * HID,
                              rmean + 2 * HID, rvar + 2 * HID, 0);

    // pooling
    k_pool_init<<<(G_NUM * HID + 255) / 256, 256>>>();
    k_pool     <<<NB_NH, 256>>>(batch);
    k_pool_fin <<<(G_NUM * HID + 255) / 256, 256>>>();

    // classifier
    k_cls<<<G_NUM, HID>>>(Wc1, bc1, Wc2, bc2, out);
}

// round 4
// speedup vs baseline: 2.5959x; 2.5959x over previous
#include <cuda_runtime.h>
#include <math.h>

#define N_NODES 100000
#define N_EDGES 1200000
#define HID 64
#define G_NUM 128
#define C_OUT 10
#define D_IN 3
#define EPS_BN 1e-5f

// -------- scratch (static device globals; no runtime allocation) --------
__device__ int   g_ecnt[N_NODES];
__device__ int   g_base[N_NODES];
__device__ int   g_fill[N_NODES];
__device__ int   g_col [N_EDGES];
__device__ int   g_tot;
__device__ float g_dinv[N_NODES];
__device__ __align__(16) float g_xw[N_NODES * HID];  // (h@W) * dinv[i]
__device__ __align__(16) float g_h [N_NODES * HID];  // layer output

// -------- init --------
__global__ void k_init() {
    int i = blockIdx.x * blockDim.x + threadIdx.x;
    if (i < N_NODES) g_ecnt[i] = 0;
    if (i == 0) g_tot = 0;
}

__global__ void k_deg(const int* __restrict__ ei) {
    int e = blockIdx.x * blockDim.x + threadIdx.x;
    if (e < N_EDGES) atomicAdd(&g_ecnt[ei[N_EDGES + e]], 1);
}

// -------- dinv + CSR bases (warp scan + one atomic per warp) --------
__global__ void k_base() {
    int i = blockIdx.x * blockDim.x + threadIdx.x;
    int lane = threadIdx.x & 31;
    int c = (i < N_NODES) ? g_ecnt[i] : 0;
    if (i < N_NODES) {
        g_dinv[i] = rsqrtf((float)(c + 1));
        g_fill[i] = 0;
    }
    int incl = c;
    #pragma unroll
    for (int off = 1; off < 32; off <<= 1) {
        int v = __shfl_up_sync(0xffffffffu, incl, off);
        if (lane >= off) incl += v;
    }
    int excl = incl - c;
    int wsum = __shfl_sync(0xffffffffu, incl, 31);
    int wbase = 0;
    if (lane == 31) wbase = atomicAdd(&g_tot, wsum);
    wbase = __shfl_sync(0xffffffffu, wbase, 31);
    if (i < N_NODES) g_base[i] = wbase + excl;
}

__global__ void k_fill(const int* __restrict__ ei) {
    int e = blockIdx.x * blockDim.x + threadIdx.x;
    if (e >= N_EDGES) return;
    int s = ei[e];
    int d = ei[N_EDGES + e];
    int pos = atomicAdd(&g_fill[d], 1);
    g_col[g_base[d] + pos] = s;
}

// -------- layer 0 linear: x[N,3] @ W0[3,64], premult dinv --------
__global__ void __launch_bounds__(256) k_lin0(const float* __restrict__ x,
                                              const float* __restrict__ W0) {
    __shared__ float sW[D_IN * HID];
    int t = threadIdx.x;
    if (t < D_IN * HID) sW[t] = W0[t];
    __syncthreads();
    int idx = blockIdx.x * blockDim.x + t;
    if (idx >= N_NODES * HID) return;
    int i = idx >> 6, j = idx & 63;
    float s = x[i * 3 + 0] * sW[j] + x[i * 3 + 1] * sW[64 + j] + x[i * 3 + 2] * sW[128 + j];
    g_xw[idx] = s * g_dinv[i];
}

// -------- hidden linear: register-tiled GEMM, 64 nodes x 64 cols / block --------
// 256 threads: thread (a,b) a=tid>>4 (node group), b=tid&15 (col group), 4x4 tile.
__global__ void __launch_bounds__(256) k_linh(const float* __restrict__ W) {
    __shared__ float sW [HID * HID];   // k-major: sW[k*64 + j]
    __shared__ float shT[HID * HID];   // transposed: shT[k*64 + node]
    int t = threadIdx.x;
    int node0 = blockIdx.x * 64;

    // load W (4096 floats) via float4
    for (int q = t; q < 1024; q += 256)
        ((float4*)sW)[q] = ((const float4*)W)[q];

    // load h tile transposed: thread (c, ln) reads float4 row chunks
    int ln = t & 63;       // node within tile
    int c0 = t >> 6;       // 0..3
    #pragma unroll
    for (int cc = c0; cc < 16; cc += 4) {
        int gi = node0 + ln;
        float4 v = make_float4(0.f, 0.f, 0.f, 0.f);
        if (gi < N_NODES) v = ((const float4*)g_h)[gi * 16 + cc];
        shT[(4 * cc + 0) * 64 + ln] = v.x;
        shT[(4 * cc + 1) * 64 + ln] = v.y;
        shT[(4 * cc + 2) * 64 + ln] = v.z;
        shT[(4 * cc + 3) * 64 + ln] = v.w;
    }
    __syncthreads();

    int a = t >> 4;   // 0..15 -> nodes 4a..4a+3
    int b = t & 15;   // 0..15 -> cols 4b..4b+3
    float4 acc0 = make_float4(0.f, 0.f, 0.f, 0.f);
    float4 acc1 = acc0, acc2 = acc0, acc3 = acc0;

    #pragma unroll 8
    for (int k = 0; k < 64; k++) {
        float4 vN = *(const float4*)&shT[k * 64 + 4 * a];
        float4 vW = *(const float4*)&sW [k * 64 + 4 * b];
        acc0.x += vN.x * vW.x; acc0.y += vN.x * vW.y; acc0.z += vN.x * vW.z; acc0.w += vN.x * vW.w;
        acc1.x += vN.y * vW.x; acc1.y += vN.y * vW.y; acc1.z += vN.y * vW.z; acc1.w += vN.y * vW.w;
        acc2.x += vN.z * vW.x; acc2.y += vN.z * vW.y; acc2.z += vN.z * vW.z; acc2.w += vN.z * vW.w;
        acc3.x += vN.w * vW.x; acc3.y += vN.w * vW.y; acc3.z += vN.w * vW.z; acc3.w += vN.w * vW.w;
    }

    float4 accs[4] = {acc0, acc1, acc2, acc3};
    #pragma unroll
    for (int r = 0; r < 4; r++) {
        int i = node0 + 4 * a + r;
        if (i < N_NODES) {
            float d = g_dinv[i];
            float4 o = accs[r];
            o.x *= d; o.y *= d; o.z *= d; o.w *= d;
            ((float4*)g_xw)[i * 16 + b] = o;
        }
    }
}

// -------- CSR gather + fused epilogue: 16 nodes x 16 threads(float4) / block ----
__global__ void __launch_bounds__(256) k_gather(const float* __restrict__ bb,
                                                const float* __restrict__ gamma,
                                                const float* __restrict__ beta,
                                                const float* __restrict__ mean,
                                                const float* __restrict__ var, int relu) {
    int t = threadIdx.x;
    int node = blockIdx.x * 16 + (t >> 4);   // N divisible by 16 -> no guard
    int j4 = t & 15;
    const float4* xw4 = (const float4*)g_xw;

    int base = g_base[node];
    int cnt  = g_ecnt[node];
    float4 acc = xw4[node * 16 + j4];        // self-loop term
    int k = 0;
    for (; k + 4 <= cnt; k += 4) {
        int s0 = __ldg(&g_col[base + k + 0]);
        int s1 = __ldg(&g_col[base + k + 1]);
        int s2 = __ldg(&g_col[base + k + 2]);
        int s3 = __ldg(&g_col[base + k + 3]);
        float4 v0 = __ldg(&xw4[s0 * 16 + j4]);
        float4 v1 = __ldg(&xw4[s1 * 16 + j4]);
        float4 v2 = __ldg(&xw4[s2 * 16 + j4]);
        float4 v3 = __ldg(&xw4[s3 * 16 + j4]);
        acc.x += (v0.x + v1.x) + (v2.x + v3.x);
        acc.y += (v0.y + v1.y) + (v2.y + v3.y);
        acc.z += (v0.z + v1.z) + (v2.z + v3.z);
        acc.w += (v0.w + v1.w) + (v2.w + v3.w);
    }
    for (; k < cnt; k++) {
        int s = __ldg(&g_col[base + k]);
        float4 v = __ldg(&xw4[s * 16 + j4]);
        acc.x += v.x; acc.y += v.y; acc.z += v.z; acc.w += v.w;
    }

    float d = g_dinv[node];
    float4 vb = ((const float4*)bb)[j4];
    float4 vg = ((const float4*)gamma)[j4];
    float4 vbt = ((const float4*)beta)[j4];
    float4 vm = ((const float4*)mean)[j4];
    float4 vv = ((const float4*)var)[j4];
    float4 o;
    o.x = (acc.x * d + vb.x - vm.x) * (vg.x * rsqrtf(vv.x + EPS_BN)) + vbt.x;
    o.y = (acc.y * d + vb.y - vm.y) * (vg.y * rsqrtf(vv.y + EPS_BN)) + vbt.y;
    o.z = (acc.z * d + vb.z - vm.z) * (vg.z * rsqrtf(vv.z + EPS_BN)) + vbt.z;
    o.w = (acc.w * d + vb.w - vm.w) * (vg.w * rsqrtf(vv.w + EPS_BN)) + vbt.w;
    if (relu) {
        o.x = fmaxf(o.x, 0.f); o.y = fmaxf(o.y, 0.f);
        o.z = fmaxf(o.z, 0.f); o.w = fmaxf(o.w, 0.f);
    }
    ((float4*)g_h)[node * 16 + j4] = o;
}

// -------- fused pooling + classifier + log_softmax: 1 block / graph -----------
// batch is sorted; node range per graph found by binary search. No atomics.
__global__ void __launch_bounds__(256) k_poolcls(const int* __restrict__ batch,
                                                 const float* __restrict__ Wc1,
                                                 const float* __restrict__ bc1,
                                                 const float* __restrict__ Wc2,
                                                 const float* __restrict__ bc2,
                                                 float* __restrict__ out) {
    __shared__ int s_se[2];
    __shared__ float ssum[16 * 65];
    __shared__ float smax[16 * 65];
    __shared__ float gv[2 * HID];
    __shared__ float hc[HID];
    __shared__ float lg[C_OUT];
    __shared__ float s_lse;

    int g = blockIdx.x;
    int t = threadIdx.x;

    if (t == 0) {
        // lower_bound(batch, g) and lower_bound(batch, g+1)
        int lo = 0, hi = N_NODES;
        while (lo < hi) { int m = (lo + hi) >> 1; if (batch[m] < g) lo = m + 1; else hi = m; }
        s_se[0] = lo;
        lo = 0; hi = N_NODES;
        while (lo < hi) { int m = (lo + hi) >> 1; if (batch[m] < g + 1) lo = m + 1; else hi = m; }
        s_se[1] = lo;
    }
    __syncthreads();
    int start = s_se[0], end = s_se[1];

    int r  = t >> 4;   // 0..15 node-lane
    int j4 = t & 15;   // float4 col group
    const float4* h4 = (const float4*)g_h;
    float4 sum = make_float4(0.f, 0.f, 0.f, 0.f);
    float4 mx  = make_float4(-INFINITY, -INFINITY, -INFINITY, -INFINITY);
    for (int i = start + r; i < end; i += 16) {
        float4 v = h4[i * 16 + j4];
        sum.x += v.x; sum.y += v.y; sum.z += v.z; sum.w += v.w;
        mx.x = fmaxf(mx.x, v.x); mx.y = fmaxf(mx.y, v.y);
        mx.z = fmaxf(mx.z, v.z); mx.w = fmaxf(mx.w, v.w);
    }
    ssum[r * 65 + 4 * j4 + 0] = sum.x; ssum[r * 65 + 4 * j4 + 1] = sum.y;
    ssum[r * 65 + 4 * j4 + 2] = sum.z; ssum[r * 65 + 4 * j4 + 3] = sum.w;
    smax[r * 65 + 4 * j4 + 0] = mx.x;  smax[r * 65 + 4 * j4 + 1] = mx.y;
    smax[r * 65 + 4 * j4 + 2] = mx.z;  smax[r * 65 + 4 * j4 + 3] = mx.w;
    __syncthreads();

    if (t < HID) {
        float s = 0.f, m = -INFINITY;
        #pragma unroll
        for (int q = 0; q < 16; q++) {
            s += ssum[q * 65 + t];
            m = fmaxf(m, smax[q * 65 + t]);
        }
        gv[t]       = s / (float)(end - start);
        gv[HID + t] = m;
    }
    __syncthreads();

    if (t < HID) {
        float s = bc1[t];
        #pragma unroll 16
        for (int k = 0; k < 2 * HID; k++) s += gv[k] * Wc1[k * HID + t];
        hc[t] = fmaxf(s, 0.f);
    }
    __syncthreads();

    if (t < C_OUT) {
        float l = bc2[t];
        #pragma unroll 16
        for (int j = 0; j < HID; j++) l += hc[j] * Wc2[j * C_OUT + t];
        lg[t] = l;
    }
    __syncthreads();

    if (t == 0) {
        float m = -INFINITY;
        #pragma unroll
        for (int c = 0; c < C_OUT; c++) m = fmaxf(m, lg[c]);
        float se = 0.f;
        #pragma unroll
        for (int c = 0; c < C_OUT; c++) se += expf(lg[c] - m);
        s_lse = m + logf(se);
    }
    __syncthreads();
    if (t < C_OUT) out[g * C_OUT + t] = lg[t] - s_lse;
}

extern "C" void kernel_launch(void* const* d_in, const int* in_sizes, int n_in,
                              void* d_out, int out_size) {
    const float* x     = (const float*)d_in[0];
    const int*   ei    = (const int*)  d_in[1];
    const int*   batch = (const int*)  d_in[2];
    // d_in[3] = num_graphs (constant 128, unused)
    const float* W0    = (const float*)d_in[4];
    const float* Ws    = (const float*)d_in[5];   // [2,64,64]
    const float* bs    = (const float*)d_in[6];   // [3,64]
    const float* gamma = (const float*)d_in[7];
    const float* beta  = (const float*)d_in[8];
    const float* rmean = (const float*)d_in[9];
    const float* rvar  = (const float*)d_in[10];
    const float* Wc1   = (const float*)d_in[11];
    const float* bc1   = (const float*)d_in[12];
    const float* Wc2   = (const float*)d_in[13];
    const float* bc2   = (const float*)d_in[14];
    float* out = (float*)d_out;

    const int NB_N    = (N_NODES + 255) / 256;
    const int NB_E    = (N_EDGES + 255) / 256;
    const int NB_NH   = (N_NODES * HID + 255) / 256;
    const int NB_GAT  = N_NODES / 16;          // 6250, exact
    const int NB_GEMM = (N_NODES + 63) / 64;   // 1563

    // CSR build + normalization
    k_init<<<NB_N, 256>>>();
    k_deg <<<NB_E, 256>>>(ei);
    k_base<<<NB_N, 256>>>();
    k_fill<<<NB_E, 256>>>(ei);

    // layer 0
    k_lin0  <<<NB_NH, 256>>>(x, W0);
    k_gather<<<NB_GAT, 256>>>(bs + 0 * HID, gamma + 0 * HID, beta + 0 * HID,
                              rmean + 0 * HID, rvar + 0 * HID, 1);
    // layer 1
    k_linh  <<<NB_GEMM, 256>>>(Ws + 0 * HID * HID);
    k_gather<<<NB_GAT, 256>>>(bs + 1 * HID, gamma + 1 * HID, beta + 1 * HID,
                              rmean + 1 * HID, rvar + 1 * HID, 1);
    // layer 2 (no relu)
    k_linh  <<<NB_GEMM, 256>>>(Ws + 1 * HID * HID);
    k_gather<<<NB_GAT, 256>>>(bs + 2 * HID, gamma + 2 * HID, beta + 2 * HID,
                              rmean + 2 * HID, rvar + 2 * HID, 0);

    // fused pooling + classifier
    k_poolcls<<<G_NUM, 256>>>(batch, Wc1, bc1, Wc2, bc2, out);
}

// round 6
// speedup vs baseline: 2.7864x; 1.0734x over previous
#include <cuda_runtime.h>
#include <cuda_fp16.h>
#include <math.h>

#define N_NODES 100000
#define N_EDGES 1200000
#define HID 64
#define G_NUM 128
#define C_OUT 10
#define D_IN 3
#define EPS_BN 1e-5f

static __device__ __forceinline__ unsigned int h2_bits(__half2 h) {
    return *reinterpret_cast<unsigned int*>(&h);
}

// -------- scratch (static device globals; no runtime allocation) --------
__device__ int   g_ecnt[N_NODES];
__device__ int   g_base[N_NODES];     // after k_base: start; after k_fill: end (= start+cnt)
__device__ int   g_col [N_EDGES];
__device__ int   g_tot;
__device__ float g_dinv[N_NODES];
__device__ __align__(16) __half g_xwh[N_NODES * HID];   // (h@W)*dinv, fp16
__device__ __align__(16) float  g_h  [N_NODES * HID];   // layer output, fp32

// -------- in-degree over real edges (4 edges/thread via int4) --------
__global__ void __launch_bounds__(256) k_deg(const int* __restrict__ ei) {
    int idx = blockIdx.x * blockDim.x + threadIdx.x;           // < E/4
    if (idx >= N_EDGES / 4) return;
    int4 d = ((const int4*)(ei + N_EDGES))[idx];
    atomicAdd(&g_ecnt[d.x], 1);
    atomicAdd(&g_ecnt[d.y], 1);
    atomicAdd(&g_ecnt[d.z], 1);
    atomicAdd(&g_ecnt[d.w], 1);
}

// -------- dinv + CSR bases (warp scan + one atomic per warp) --------
__global__ void k_base() {
    int i = blockIdx.x * blockDim.x + threadIdx.x;
    int lane = threadIdx.x & 31;
    int c = (i < N_NODES) ? g_ecnt[i] : 0;
    if (i < N_NODES) g_dinv[i] = rsqrtf((float)(c + 1));
    int incl = c;
    #pragma unroll
    for (int off = 1; off < 32; off <<= 1) {
        int v = __shfl_up_sync(0xffffffffu, incl, off);
        if (lane >= off) incl += v;
    }
    int excl = incl - c;
    int wsum = __shfl_sync(0xffffffffu, incl, 31);
    int wbase = 0;
    if (lane == 31) wbase = atomicAdd(&g_tot, wsum);
    wbase = __shfl_sync(0xffffffffu, wbase, 31);
    if (i < N_NODES) g_base[i] = wbase + excl;
}

// -------- CSR fill: cursor IS g_base (ends at start+cnt); 2 edges/thread ------
__global__ void __launch_bounds__(256) k_fill(const int* __restrict__ ei) {
    int idx = blockIdx.x * blockDim.x + threadIdx.x;           // < E/2
    if (idx >= N_EDGES / 2) return;
    int2 s = ((const int2*)ei)[idx];
    int2 d = ((const int2*)(ei + N_EDGES))[idx];
    int p0 = atomicAdd(&g_base[d.x], 1); g_col[p0] = s.x;
    int p1 = atomicAdd(&g_base[d.y], 1); g_col[p1] = s.y;
}

// -------- layer 0 linear: x[N,3] @ W0[3,64] * dinv -> fp16, 4 cols/thread -----
__global__ void __launch_bounds__(256) k_lin0(const float* __restrict__ x,
                                              const float* __restrict__ W0) {
    __shared__ float sW[D_IN * HID];
    int t = threadIdx.x;
    if (t < D_IN * HID) sW[t] = W0[t];
    __syncthreads();
    int idx = blockIdx.x * blockDim.x + t;                     // < N*16
    if (idx >= N_NODES * 16) return;
    int i = idx >> 4, j4 = idx & 15;
    float x0 = x[i * 3 + 0], x1 = x[i * 3 + 1], x2 = x[i * 3 + 2];
    float d = g_dinv[i];
    float o[4];
    #pragma unroll
    for (int q = 0; q < 4; q++) {
        int j = 4 * j4 + q;
        o[q] = (x0 * sW[j] + x1 * sW[64 + j] + x2 * sW[128 + j]) * d;
    }
    uint2 pk;
    pk.x = h2_bits(__floats2half2_rn(o[0], o[1]));
    pk.y = h2_bits(__floats2half2_rn(o[2], o[3]));
    ((uint2*)g_xwh)[idx] = pk;
}

// -------- hidden linear: register-tiled GEMM, 64x64/block, fp16 output -------
__global__ void __launch_bounds__(256) k_linh(const float* __restrict__ W) {
    __shared__ float sW [HID * HID];   // k-major: sW[k*64 + j]
    __shared__ float shT[HID * HID];   // transposed: shT[k*64 + node]
    int t = threadIdx.x;
    int node0 = blockIdx.x * 64;

    for (int q = t; q < 1024; q += 256)
        ((float4*)sW)[q] = ((const float4*)W)[q];

    int ln = t & 63;
    int c0 = t >> 6;
    #pragma unroll
    for (int cc = c0; cc < 16; cc += 4) {
        int gi = node0 + ln;
        float4 v = make_float4(0.f, 0.f, 0.f, 0.f);
        if (gi < N_NODES) v = ((const float4*)g_h)[gi * 16 + cc];
        shT[(4 * cc + 0) * 64 + ln] = v.x;
        shT[(4 * cc + 1) * 64 + ln] = v.y;
        shT[(4 * cc + 2) * 64 + ln] = v.z;
        shT[(4 * cc + 3) * 64 + ln] = v.w;
    }
    __syncthreads();

    int a = t >> 4;
    int b = t & 15;
    float4 acc0 = make_float4(0.f, 0.f, 0.f, 0.f);
    float4 acc1 = acc0, acc2 = acc0, acc3 = acc0;

    #pragma unroll 8
    for (int k = 0; k < 64; k++) {
        float4 vN = *(const float4*)&shT[k * 64 + 4 * a];
        float4 vW = *(const float4*)&sW [k * 64 + 4 * b];
        acc0.x += vN.x * vW.x; acc0.y += vN.x * vW.y; acc0.z += vN.x * vW.z; acc0.w += vN.x * vW.w;
        acc1.x += vN.y * vW.x; acc1.y += vN.y * vW.y; acc1.z += vN.y * vW.z; acc1.w += vN.y * vW.w;
        acc2.x += vN.z * vW.x; acc2.y += vN.z * vW.y; acc2.z += vN.z * vW.z; acc2.w += vN.z * vW.w;
        acc3.x += vN.w * vW.x; acc3.y += vN.w * vW.y; acc3.z += vN.w * vW.z; acc3.w += vN.w * vW.w;
    }

    float4 accs[4] = {acc0, acc1, acc2, acc3};
    #pragma unroll
    for (int r = 0; r < 4; r++) {
        int i = node0 + 4 * a + r;
        if (i < N_NODES) {
            float d = g_dinv[i];
            float4 o = accs[r];
            uint2 pk;
            pk.x = h2_bits(__floats2half2_rn(o.x * d, o.y * d));
            pk.y = h2_bits(__floats2half2_rn(o.z * d, o.w * d));
            ((uint2*)g_xwh)[i * 16 + b] = pk;
        }
    }
}

// -------- CSR gather (fp16 rows, fp32 accum) + fused BN epilogue --------------
__global__ void __launch_bounds__(256) k_gather(const float* __restrict__ bb,
                                                const float* __restrict__ gamma,
                                                const float* __restrict__ beta,
                                                const float* __restrict__ mean,
                                                const float* __restrict__ var, int relu) {
    int t = threadIdx.x;
    int node = blockIdx.x * 16 + (t >> 4);   // N divisible by 16
    int j4 = t & 15;
    const uint2* xw2 = (const uint2*)g_xwh;

    int cnt  = g_ecnt[node];
    int base = g_base[node] - cnt;           // g_base holds segment end after fill

    uint2 self = xw2[node * 16 + j4];
    float2 slo = __half22float2(*(const __half2*)&self.x);
    float2 shi = __half22float2(*(const __half2*)&self.y);
    float4 acc = make_float4(slo.x, slo.y, shi.x, shi.y);

    int k = 0;
    for (; k + 4 <= cnt; k += 4) {
        int s0 = __ldg(&g_col[base + k + 0]);
        int s1 = __ldg(&g_col[base + k + 1]);
        int s2 = __ldg(&g_col[base + k + 2]);
        int s3 = __ldg(&g_col[base + k + 3]);
        uint2 r0 = __ldg(&xw2[s0 * 16 + j4]);
        uint2 r1 = __ldg(&xw2[s1 * 16 + j4]);
        uint2 r2 = __ldg(&xw2[s2 * 16 + j4]);
        uint2 r3 = __ldg(&xw2[s3 * 16 + j4]);
        float2 a0 = __half22float2(*(const __half2*)&r0.x), b0 = __half22float2(*(const __half2*)&r0.y);
        float2 a1 = __half22float2(*(const __half2*)&r1.x), b1 = __half22float2(*(const __half2*)&r1.y);
        float2 a2 = __half22float2(*(const __half2*)&r2.x), b2 = __half22float2(*(const __half2*)&r2.y);
        float2 a3 = __half22float2(*(const __half2*)&r3.x), b3 = __half22float2(*(const __half2*)&r3.y);
        acc.x += (a0.x + a1.x) + (a2.x + a3.x);
        acc.y += (a0.y + a1.y) + (a2.y + a3.y);
        acc.z += (b0.x + b1.x) + (b2.x + b3.x);
        acc.w += (b0.y + b1.y) + (b2.y + b3.y);
    }
    for (; k < cnt; k++) {
        int s = __ldg(&g_col[base + k]);
        uint2 r = __ldg(&xw2[s * 16 + j4]);
        float2 a = __half22float2(*(const __half2*)&r.x);
        float2 b = __half22float2(*(const __half2*)&r.y);
        acc.x += a.x; acc.y += a.y; acc.z += b.x; acc.w += b.y;
    }

    float d = g_dinv[node];
    float4 vb  = ((const float4*)bb)[j4];
    float4 vg  = ((const float4*)gamma)[j4];
    float4 vbt = ((const float4*)beta)[j4];
    float4 vm  = ((const float4*)mean)[j4];
    float4 vv  = ((const float4*)var)[j4];
    float4 o;
    o.x = (acc.x * d + vb.x - vm.x) * (vg.x * rsqrtf(vv.x + EPS_BN)) + vbt.x;
    o.y = (acc.y * d + vb.y - vm.y) * (vg.y * rsqrtf(vv.y + EPS_BN)) + vbt.y;
    o.z = (acc.z * d + vb.z - vm.z) * (vg.z * rsqrtf(vv.z + EPS_BN)) + vbt.z;
    o.w = (acc.w * d + vb.w - vm.w) * (vg.w * rsqrtf(vv.w + EPS_BN)) + vbt.w;
    if (relu) {
        o.x = fmaxf(o.x, 0.f); o.y = fmaxf(o.y, 0.f);
        o.z = fmaxf(o.z, 0.f); o.w = fmaxf(o.w, 0.f);
    }
    ((float4*)g_h)[node * 16 + j4] = o;
}

// -------- fused pooling + classifier + log_softmax: 1 block / graph -----------
__global__ void __launch_bounds__(256) k_poolcls(const int* __restrict__ batch,
                                                 const float* __restrict__ Wc1,
                                                 const float* __restrict__ bc1,
                                                 const float* __restrict__ Wc2,
                                                 const float* __restrict__ bc2,
                                                 float* __restrict__ out) {
    __shared__ int s_se[2];
    __shared__ float ssum[16 * 65];
    __shared__ float smax[16 * 65];
    __shared__ float gv[2 * HID];
    __shared__ float hc[HID];
    __shared__ float lg[C_OUT];
    __shared__ float s_lse;

    int g = blockIdx.x;
    int t = threadIdx.x;

    if (t == 0) {
        int lo = 0, hi = N_NODES;
        while (lo < hi) { int m = (lo + hi) >> 1; if (batch[m] < g) lo = m + 1; else hi = m; }
        s_se[0] = lo;
        lo = 0; hi = N_NODES;
        while (lo < hi) { int m = (lo + hi) >> 1; if (batch[m] < g + 1) lo = m + 1; else hi = m; }
        s_se[1] = lo;
    }
    __syncthreads();
    int start = s_se[0], end = s_se[1];

    int r  = t >> 4;
    int j4 = t & 15;
    const float4* h4 = (const float4*)g_h;
    float4 sum = make_float4(0.f, 0.f, 0.f, 0.f);
    float4 mx  = make_float4(-INFINITY, -INFINITY, -INFINITY, -INFINITY);
    for (int i = start + r; i < end; i += 16) {
        float4 v = h4[i * 16 + j4];
        sum.x += v.x; sum.y += v.y; sum.z += v.z; sum.w += v.w;
        mx.x = fmaxf(mx.x, v.x); mx.y = fmaxf(mx.y, v.y);
        mx.z = fmaxf(mx.z, v.z); mx.w = fmaxf(mx.w, v.w);
    }
    ssum[r * 65 + 4 * j4 + 0] = sum.x; ssum[r * 65 + 4 * j4 + 1] = sum.y;
    ssum[r * 65 + 4 * j4 + 2] = sum.z; ssum[r * 65 + 4 * j4 + 3] = sum.w;
    smax[r * 65 + 4 * j4 + 0] = mx.x;  smax[r * 65 + 4 * j4 + 1] = mx.y;
    smax[r * 65 + 4 * j4 + 2] = mx.z;  smax[r * 65 + 4 * j4 + 3] = mx.w;
    __syncthreads();

    if (t < HID) {
        float s = 0.f, m = -INFINITY;
        #pragma unroll
        for (int q = 0; q < 16; q++) {
            s += ssum[q * 65 + t];
            m = fmaxf(m, smax[q * 65 + t]);
        }
        gv[t]       = s / (float)(end - start);
        gv[HID + t] = m;
    }
    __syncthreads();

    if (t < HID) {
        float s = bc1[t];
        #pragma unroll 16
        for (int k = 0; k < 2 * HID; k++) s += gv[k] * Wc1[k * HID + t];
        hc[t] = fmaxf(s, 0.f);
    }
    __syncthreads();

    if (t < C_OUT) {
        float l = bc2[t];
        #pragma unroll 16
        for (int j = 0; j < HID; j++) l += hc[j] * Wc2[j * C_OUT + t];
        lg[t] = l;
    }
    __syncthreads();

    if (t == 0) {
        float m = -INFINITY;
        #pragma unroll
        for (int c = 0; c < C_OUT; c++) m = fmaxf(m, lg[c]);
        float se = 0.f;
        #pragma unroll
        for (int c = 0; c < C_OUT; c++) se += expf(lg[c] - m);
        s_lse = m + logf(se);
    }
    __syncthreads();
    if (t < C_OUT) out[g * C_OUT + t] = lg[t] - s_lse;
}

extern "C" void kernel_launch(void* const* d_in, const int* in_sizes, int n_in,
                              void* d_out, int out_size) {
    const float* x     = (const float*)d_in[0];
    const int*   ei    = (const int*)  d_in[1];
    const int*   batch = (const int*)  d_in[2];
    // d_in[3] = num_graphs (constant 128, unused)
    const float* W0    = (const float*)d_in[4];
    const float* Ws    = (const float*)d_in[5];
    const float* bs    = (const float*)d_in[6];
    const float* gamma = (const float*)d_in[7];
    const float* beta  = (const float*)d_in[8];
    const float* rmean = (const float*)d_in[9];
    const float* rvar  = (const float*)d_in[10];
    const float* Wc1   = (const float*)d_in[11];
    const float* bc1   = (const float*)d_in[12];
    const float* Wc2   = (const float*)d_in[13];
    const float* bc2   = (const float*)d_in[14];
    float* out = (float*)d_out;

    const int NB_N    = (N_NODES + 255) / 256;
    const int NB_E4   = (N_EDGES / 4 + 255) / 256;
    const int NB_E2   = (N_EDGES / 2 + 255) / 256;
    const int NB_L0   = (N_NODES * 16 + 255) / 256;
    const int NB_GAT  = N_NODES / 16;
    const int NB_GEMM = (N_NODES + 63) / 64;

    // zero-init counters via graph memset nodes
    void* p_ecnt = 0; void* p_tot = 0;
    cudaGetSymbolAddress(&p_ecnt, g_ecnt);
    cudaGetSymbolAddress(&p_tot,  g_tot);
    cudaMemsetAsync(p_ecnt, 0, N_NODES * sizeof(int));
    cudaMemsetAsync(p_tot,  0, sizeof(int));

    // CSR build
    k_deg <<<NB_E4, 256>>>(ei);
    k_base<<<NB_N, 256>>>();
    k_fill<<<NB_E2, 256>>>(ei);

    // layer 0
    k_lin0  <<<NB_L0, 256>>>(x, W0);
    k_gather<<<NB_GAT, 256>>>(bs + 0 * HID, gamma + 0 * HID, beta + 0 * HID,
                              rmean + 0 * HID, rvar + 0 * HID, 1);
    // layer 1
    k_linh  <<<NB_GEMM, 256>>>(Ws + 0 * HID * HID);
    k_gather<<<NB_GAT, 256>>>(bs + 1 * HID, gamma + 1 * HID, beta + 1 * HID,
                              rmean + 1 * HID, rvar + 1 * HID, 1);
    // layer 2 (no relu)
    k_linh  <<<NB_GEMM, 256>>>(Ws + 1 * HID * HID);
    k_gather<<<NB_GAT, 256>>>(bs + 2 * HID, gamma + 2 * HID, beta + 2 * HID,
                              rmean + 2 * HID, rvar + 2 * HID, 0);

    // fused pooling + classifier
    k_poolcls<<<G_NUM, 256>>>(batch, Wc1, bc1, Wc2, bc2, out);
}

// round 7
// speedup vs baseline: 2.8730x; 1.0311x over previous
#include <cuda_runtime.h>
#include <cuda_fp16.h>
#include <math.h>

#define N_NODES 100000
#define N_EDGES 1200000
#define COL_CAP (N_EDGES + 3 * N_NODES + 16)
#define HID 64
#define G_NUM 128
#define C_OUT 10
#define D_IN 3
#define EPS_BN 1e-5f

static __device__ __forceinline__ unsigned int h2_bits(__half2 h) {
    return *reinterpret_cast<unsigned int*>(&h);
}
static __device__ __forceinline__ __half2 bits_h2(unsigned int u) {
    return *reinterpret_cast<__half2*>(&u);
}

// -------- scratch (static device globals; no runtime allocation) --------
__device__ int   g_ecnt[N_NODES];
__device__ int   g_base[N_NODES];     // after k_base: aligned start; after k_fill: start+cnt
__device__ __align__(16) int g_col[COL_CAP];
__device__ int   g_tot;
__device__ float g_dinv[N_NODES];
__device__ __align__(16) __half g_xwh[N_NODES * HID];   // (h@W)*dinv, fp16
__device__ __align__(16) float  g_h  [N_NODES * HID];   // layer output, fp32

// -------- in-degree over real edges (4 edges/thread via int4) --------
__global__ void __launch_bounds__(256) k_deg(const int* __restrict__ ei) {
    int idx = blockIdx.x * blockDim.x + threadIdx.x;           // < E/4
    if (idx >= N_EDGES / 4) return;
    int4 d = ((const int4*)(ei + N_EDGES))[idx];
    atomicAdd(&g_ecnt[d.x], 1);
    atomicAdd(&g_ecnt[d.y], 1);
    atomicAdd(&g_ecnt[d.z], 1);
    atomicAdd(&g_ecnt[d.w], 1);
}

// -------- dinv + CSR bases, 4-aligned allocations (warp scan + atomic) --------
__global__ void k_base() {
    int i = blockIdx.x * blockDim.x + threadIdx.x;
    int lane = threadIdx.x & 31;
    int c = (i < N_NODES) ? g_ecnt[i] : 0;
    if (i < N_NODES) g_dinv[i] = rsqrtf((float)(c + 1));
    int alloc = (c + 3) & ~3;          // pad to multiple of 4 -> 16B-aligned segments
    int incl = alloc;
    #pragma unroll
    for (int off = 1; off < 32; off <<= 1) {
        int v = __shfl_up_sync(0xffffffffu, incl, off);
        if (lane >= off) incl += v;
    }
    int excl = incl - alloc;
    int wsum = __shfl_sync(0xffffffffu, incl, 31);
    int wbase = 0;
    if (lane == 31) wbase = atomicAdd(&g_tot, wsum);
    wbase = __shfl_sync(0xffffffffu, wbase, 31);
    if (i < N_NODES) g_base[i] = wbase + excl;
}

// -------- CSR fill: cursor IS g_base (ends at start+cnt); 2 edges/thread ------
__global__ void __launch_bounds__(256) k_fill(const int* __restrict__ ei) {
    int idx = blockIdx.x * blockDim.x + threadIdx.x;           // < E/2
    if (idx >= N_EDGES / 2) return;
    int2 s = ((const int2*)ei)[idx];
    int2 d = ((const int2*)(ei + N_EDGES))[idx];
    int p0 = atomicAdd(&g_base[d.x], 1); g_col[p0] = s.x;
    int p1 = atomicAdd(&g_base[d.y], 1); g_col[p1] = s.y;
}

// -------- layer 0 linear: x[N,3] @ W0[3,64] * dinv -> fp16, 4 cols/thread -----
__global__ void __launch_bounds__(256) k_lin0(const float* __restrict__ x,
                                              const float* __restrict__ W0) {
    __shared__ float sW[D_IN * HID];
    int t = threadIdx.x;
    if (t < D_IN * HID) sW[t] = W0[t];
    __syncthreads();
    int idx = blockIdx.x * blockDim.x + t;                     // < N*16
    if (idx >= N_NODES * 16) return;
    int i = idx >> 4, j4 = idx & 15;
    float x0 = x[i * 3 + 0], x1 = x[i * 3 + 1], x2 = x[i * 3 + 2];
    float d = g_dinv[i];
    float o[4];
    #pragma unroll
    for (int q = 0; q < 4; q++) {
        int j = 4 * j4 + q;
        o[q] = (x0 * sW[j] + x1 * sW[64 + j] + x2 * sW[128 + j]) * d;
    }
    uint2 pk;
    pk.x = h2_bits(__floats2half2_rn(o[0], o[1]));
    pk.y = h2_bits(__floats2half2_rn(o[2], o[3]));
    ((uint2*)g_xwh)[idx] = pk;
}

// -------- hidden linear: register-tiled GEMM, 64x64/block, fp16 output -------
__global__ void __launch_bounds__(256) k_linh(const float* __restrict__ W) {
    __shared__ float sW [HID * HID];   // k-major: sW[k*64 + j]
    __shared__ float shT[HID * HID];   // transposed: shT[k*64 + node]
    int t = threadIdx.x;
    int node0 = blockIdx.x * 64;

    for (int q = t; q < 1024; q += 256)
        ((float4*)sW)[q] = ((const float4*)W)[q];

    int ln = t & 63;
    int c0 = t >> 6;
    #pragma unroll
    for (int cc = c0; cc < 16; cc += 4) {
        int gi = node0 + ln;
        float4 v = make_float4(0.f, 0.f, 0.f, 0.f);
        if (gi < N_NODES) v = ((const float4*)g_h)[gi * 16 + cc];
        shT[(4 * cc + 0) * 64 + ln] = v.x;
        shT[(4 * cc + 1) * 64 + ln] = v.y;
        shT[(4 * cc + 2) * 64 + ln] = v.z;
        shT[(4 * cc + 3) * 64 + ln] = v.w;
    }
    __syncthreads();

    int a = t >> 4;
    int b = t & 15;
    float4 acc0 = make_float4(0.f, 0.f, 0.f, 0.f);
    float4 acc1 = acc0, acc2 = acc0, acc3 = acc0;

    #pragma unroll 8
    for (int k = 0; k < 64; k++) {
        float4 vN = *(const float4*)&shT[k * 64 + 4 * a];
        float4 vW = *(const float4*)&sW [k * 64 + 4 * b];
        acc0.x += vN.x * vW.x; acc0.y += vN.x * vW.y; acc0.z += vN.x * vW.z; acc0.w += vN.x * vW.w;
        acc1.x += vN.y * vW.x; acc1.y += vN.y * vW.y; acc1.z += vN.y * vW.z; acc1.w += vN.y * vW.w;
        acc2.x += vN.z * vW.x; acc2.y += vN.z * vW.y; acc2.z += vN.z * vW.z; acc2.w += vN.z * vW.w;
        acc3.x += vN.w * vW.x; acc3.y += vN.w * vW.y; acc3.z += vN.w * vW.z; acc3.w += vN.w * vW.w;
    }

    float4 accs[4] = {acc0, acc1, acc2, acc3};
    #pragma unroll
    for (int r = 0; r < 4; r++) {
        int i = node0 + 4 * a + r;
        if (i < N_NODES) {
            float d = g_dinv[i];
            float4 o = accs[r];
            uint2 pk;
            pk.x = h2_bits(__floats2half2_rn(o.x * d, o.y * d));
            pk.y = h2_bits(__floats2half2_rn(o.z * d, o.w * d));
            ((uint2*)g_xwh)[i * 16 + b] = pk;
        }
    }
}

// -------- CSR gather: int4 cols + half2 tree accum + fused BN epilogue --------
__global__ void __launch_bounds__(256) k_gather(const float* __restrict__ bb,
                                                const float* __restrict__ gamma,
                                                const float* __restrict__ beta,
                                                const float* __restrict__ mean,
                                                const float* __restrict__ var, int relu) {
    int t = threadIdx.x;
    int node = blockIdx.x * 16 + (t >> 4);   // N divisible by 16
    int j4 = t & 15;
    const uint2* xw2 = (const uint2*)g_xwh;

    int cnt  = g_ecnt[node];
    int base = g_base[node] - cnt;           // cursor ended at start+cnt; start is 4-aligned

    uint2 self = xw2[node * 16 + j4];
    float2 slo = __half22float2(bits_h2(self.x));
    float2 shi = __half22float2(bits_h2(self.y));
    float4 acc = make_float4(slo.x, slo.y, shi.x, shi.y);

    const int4* c4p = (const int4*)(g_col + base);   // 16B-aligned
    int k = 0;
    for (; k + 4 <= cnt; k += 4) {
        int4 c4 = __ldg(&c4p[k >> 2]);
        uint2 r0 = __ldg(&xw2[c4.x * 16 + j4]);
        uint2 r1 = __ldg(&xw2[c4.y * 16 + j4]);
        uint2 r2 = __ldg(&xw2[c4.z * 16 + j4]);
        uint2 r3 = __ldg(&xw2[c4.w * 16 + j4]);
        __half2 lo = __hadd2(__hadd2(bits_h2(r0.x), bits_h2(r1.x)),
                             __hadd2(bits_h2(r2.x), bits_h2(r3.x)));
        __half2 hi = __hadd2(__hadd2(bits_h2(r0.y), bits_h2(r1.y)),
                             __hadd2(bits_h2(r2.y), bits_h2(r3.y)));
        float2 flo = __half22float2(lo);
        float2 fhi = __half22float2(hi);
        acc.x += flo.x; acc.y += flo.y; acc.z += fhi.x; acc.w += fhi.y;
    }
    for (; k < cnt; k++) {
        int s = __ldg(&g_col[base + k]);
        uint2 r = __ldg(&xw2[s * 16 + j4]);
        float2 a = __half22float2(bits_h2(r.x));
        float2 b = __half22float2(bits_h2(r.y));
        acc.x += a.x; acc.y += a.y; acc.z += b.x; acc.w += b.y;
    }

    float d = g_dinv[node];
    float4 vb  = ((const float4*)bb)[j4];
    float4 vg  = ((const float4*)gamma)[j4];
    float4 vbt = ((const float4*)beta)[j4];
    float4 vm  = ((const float4*)mean)[j4];
    float4 vv  = ((const float4*)var)[j4];
    float4 o;
    o.x = (acc.x * d + vb.x - vm.x) * (vg.x * rsqrtf(vv.x + EPS_BN)) + vbt.x;
    o.y = (acc.y * d + vb.y - vm.y) * (vg.y * rsqrtf(vv.y + EPS_BN)) + vbt.y;
    o.z = (acc.z * d + vb.z - vm.z) * (vg.z * rsqrtf(vv.z + EPS_BN)) + vbt.z;
    o.w = (acc.w * d + vb.w - vm.w) * (vg.w * rsqrtf(vv.w + EPS_BN)) + vbt.w;
    if (relu) {
        o.x = fmaxf(o.x, 0.f); o.y = fmaxf(o.y, 0.f);
        o.z = fmaxf(o.z, 0.f); o.w = fmaxf(o.w, 0.f);
    }
    ((float4*)g_h)[node * 16 + j4] = o;
}

// -------- fused pooling + classifier + log_softmax: 1 block / graph -----------
__global__ void __launch_bounds__(256) k_poolcls(const int* __restrict__ batch,
                                                 const float* __restrict__ Wc1,
                                                 const float* __restrict__ bc1,
                                                 const float* __restrict__ Wc2,
                                                 const float* __restrict__ bc2,
                                                 float* __restrict__ out) {
    __shared__ int s_se[2];
    __shared__ float ssum[16 * 65];
    __shared__ float smax[16 * 65];
    __shared__ float gv[2 * HID];
    __shared__ float hc[HID];
    __shared__ float lg[C_OUT];
    __shared__ float s_lse;

    int g = blockIdx.x;
    int t = threadIdx.x;

    if (t == 0) {
        int lo = 0, hi = N_NODES;
        while (lo < hi) { int m = (lo + hi) >> 1; if (batch[m] < g) lo = m + 1; else hi = m; }
        s_se[0] = lo;
        lo = 0; hi = N_NODES;
        while (lo < hi) { int m = (lo + hi) >> 1; if (batch[m] < g + 1) lo = m + 1; else hi = m; }
        s_se[1] = lo;
    }
    __syncthreads();
    int start = s_se[0], end = s_se[1];

    int r  = t >> 4;
    int j4 = t & 15;
    const float4* h4 = (const float4*)g_h;
    float4 sum = make_float4(0.f, 0.f, 0.f, 0.f);
    float4 mx  = make_float4(-INFINITY, -INFINITY, -INFINITY, -INFINITY);
    for (int i = start + r; i < end; i += 16) {
        float4 v = h4[i * 16 + j4];
        sum.x += v.x; sum.y += v.y; sum.z += v.z; sum.w += v.w;
        mx.x = fmaxf(mx.x, v.x); mx.y = fmaxf(mx.y, v.y);
        mx.z = fmaxf(mx.z, v.z); mx.w = fmaxf(mx.w, v.w);
    }
    ssum[r * 65 + 4 * j4 + 0] = sum.x; ssum[r * 65 + 4 * j4 + 1] = sum.y;
    ssum[r * 65 + 4 * j4 + 2] = sum.z; ssum[r * 65 + 4 * j4 + 3] = sum.w;
    smax[r * 65 + 4 * j4 + 0] = mx.x;  smax[r * 65 + 4 * j4 + 1] = mx.y;
    smax[r * 65 + 4 * j4 + 2] = mx.z;  smax[r * 65 + 4 * j4 + 3] = mx.w;
    __syncthreads();

    if (t < HID) {
        float s = 0.f, m = -INFINITY;
        #pragma unroll
        for (int q = 0; q < 16; q++) {
            s += ssum[q * 65 + t];
            m = fmaxf(m, smax[q * 65 + t]);
        }
        gv[t]       = s / (float)(end - start);
        gv[HID + t] = m;
    }
    __syncthreads();

    if (t < HID) {
        float s = bc1[t];
        #pragma unroll 16
        for (int k = 0; k < 2 * HID; k++) s += gv[k] * Wc1[k * HID + t];
        hc[t] = fmaxf(s, 0.f);
    }
    __syncthreads();

    if (t < C_OUT) {
        float l = bc2[t];
        #pragma unroll 16
        for (int j = 0; j < HID; j++) l += hc[j] * Wc2[j * C_OUT + t];
        lg[t] = l;
    }
    __syncthreads();

    if (t == 0) {
        float m = -INFINITY;
        #pragma unroll
        for (int c = 0; c < C_OUT; c++) m = fmaxf(m, lg[c]);
        float se = 0.f;
        #pragma unroll
        for (int c = 0; c < C_OUT; c++) se += expf(lg[c] - m);
        s_lse = m + logf(se);
    }
    __syncthreads();
    if (t < C_OUT) out[g * C_OUT + t] = lg[t] - s_lse;
}

extern "C" void kernel_launch(void* const* d_in, const int* in_sizes, int n_in,
                              void* d_out, int out_size) {
    const float* x     = (const float*)d_in[0];
    const int*   ei    = (const int*)  d_in[1];
    const int*   batch = (const int*)  d_in[2];
    // d_in[3] = num_graphs (constant 128, unused)
    const float* W0    = (const float*)d_in[4];
    const float* Ws    = (const float*)d_in[5];
    const float* bs    = (const float*)d_in[6];
    const float* gamma = (const float*)d_in[7];
    const float* beta  = (const float*)d_in[8];
    const float* rmean = (const float*)d_in[9];
    const float* rvar  = (const float*)d_in[10];
    const float* Wc1   = (const float*)d_in[11];
    const float* bc1   = (const float*)d_in[12];
    const float* Wc2   = (const float*)d_in[13];
    const float* bc2   = (const float*)d_in[14];
    float* out = (float*)d_out;

    const int NB_N    = (N_NODES + 255) / 256;
    const int NB_E4   = (N_EDGES / 4 + 255) / 256;
    const int NB_E2   = (N_EDGES / 2 + 255) / 256;
    const int NB_L0   = (N_NODES * 16 + 255) / 256;
    const int NB_GAT  = N_NODES / 16;
    const int NB_GEMM = (N_NODES + 63) / 64;

    // zero-init counters via graph memset nodes
    void* p_ecnt = 0; void* p_tot = 0;
    cudaGetSymbolAddress(&p_ecnt, g_ecnt);
    cudaGetSymbolAddress(&p_tot,  g_tot);
    cudaMemsetAsync(p_ecnt, 0, N_NODES * sizeof(int));
    cudaMemsetAsync(p_tot,  0, sizeof(int));

    // CSR build
    k_deg <<<NB_E4, 256>>>(ei);
    k_base<<<NB_N, 256>>>();
    k_fill<<<NB_E2, 256>>>(ei);

    // layer 0
    k_lin0  <<<NB_L0, 256>>>(x, W0);
    k_gather<<<NB_GAT, 256>>>(bs + 0 * HID, gamma + 0 * HID, beta + 0 * HID,
                              rmean + 0 * HID, rvar + 0 * HID, 1);
    // layer 1
    k_linh  <<<NB_GEMM, 256>>>(Ws + 0 * HID * HID);
    k_gather<<<NB_GAT, 256>>>(bs + 1 * HID, gamma + 1 * HID, beta + 1 * HID,
                              rmean + 1 * HID, rvar + 1 * HID, 1);
    // layer 2 (no relu)
    k_linh  <<<NB_GEMM, 256>>>(Ws + 1 * HID * HID);
    k_gather<<<NB_GAT, 256>>>(bs + 2 * HID, gamma + 2 * HID, beta + 2 * HID,
                              rmean + 2 * HID, rvar + 2 * HID, 0);

    // fused pooling + classifier
    k_poolcls<<<G_NUM, 256>>>(batch, Wc1, bc1, Wc2, bc2, out);
}